// round 15
// baseline (speedup 1.0000x reference)
#include <cuda_runtime.h>
#include <cuda_bf16.h>
#include <cuda_fp16.h>
#include <cstdint>

// ============================================================================
// Mixed-precision HMMA pipeline. All GEMMs NT: D[m][n] = sum_k A[m][k]B[n][k].
//  - Pre-softmax path: split-bf16 3-term (AhBh+AhBl+AlBh), fp32 accum.
//    NEW: 128x128x32 tile, 128 thr, 2-stage, 2 CTAs/SM (fp16-kernel recipe).
//  - v-chain + post-softmax: fp16 1-term. 128x128x64, 3-stage, 2 CTAs/SM.
// Logit path: logits ~ 0.125*(qkv_q.H.qkv_k^T) + 0.125*beta, H = Wk^T Wq.
// Dual-stream fork-join schedule + split-K x2 logits.
// ============================================================================

// bf16 3-term kernel: 128x128x32, PADK2=40 (80B rows)
#define BKB 32
#define PADK2 40
#define T2_ELT (128 * PADK2)            // 5120
#define STG2_ELT (4 * T2_ELT)           // 20480 (Ah,Al,Bh,Bl)
#define STG2_BYTES (STG2_ELT * 2)       // 40960
#define SMEM_REQ2 (2 * STG2_BYTES)      // 81920 -> 2 CTAs/SM
#define OFF2_AL (T2_ELT * 2)
#define OFF2_BH (2 * T2_ELT * 2)
#define OFF2_BL (3 * T2_ELT * 2)

// fp16 kernel: 128x128x64, PADK=72 (144B rows), 3 stages
#define PADK 72
#define AH_TILE_ELT (128 * PADK)
#define STG_ELT_H (2 * AH_TILE_ELT)
#define STG_BYTES_H (STG_ELT_H * 2)
#define SMEM_REQ_H (3 * STG_BYTES_H)
#define OFF_B_H (AH_TILE_ELT * 2)

// ---- scratch (device globals) ----------------------------------------------
__device__ __align__(256) __nv_bfloat16 g_xT_hi[33554432],  g_xT_lo[33554432];
__device__ __align__(256) __half        g_xT_f[33554432];
__device__ __align__(256) __nv_bfloat16 g_Wqkv_hi[33554432],g_Wqkv_lo[33554432];
__device__ __align__(256) __half        g_Wqkv_vf[16777216];
__device__ __align__(256) __nv_bfloat16 g_WqT_hi[16777216], g_WqT_lo[16777216];
__device__ __align__(256) __nv_bfloat16 g_WkT_hi[16777216], g_WkT_lo[16777216];
__device__ __align__(256) __half        g_Wv_f[16777216],   g_Wout_f[16777216];
__device__ __align__(256) __nv_bfloat16 g_qkv_hi[67108864], g_qkv_lo[67108864];
__device__ __align__(256) __half        g_v_f[33554432];
__device__ __align__(256) __nv_bfloat16 g_q2_hi[33554432],  g_q2_lo[33554432];
__device__ __align__(256) __nv_bfloat16 g_H_hi[16777216],   g_H_lo[16777216];
__device__ __align__(256) __half        g_v2T_f[33554432];
__device__ __align__(256) __half        g_attn_f[4194304];
__device__ __align__(256) __half        g_outT_f[33554432];
__device__ __align__(256) float g_dot[4194304];
__device__ __align__(256) float g_dot2[4194304];
__device__ __align__(256) float g_wvec[4096];
__device__ __align__(256) float g_beta[8192];

// ---- helpers ----------------------------------------------------------------
__device__ __forceinline__ uint32_t smem_u32(const void* p) {
    uint32_t r;
    asm("{ .reg .u64 t; cvta.to.shared.u64 t, %1; cvt.u32.u64 %0, t; }" : "=r"(r) : "l"(p));
    return r;
}
__device__ __forceinline__ void cpasync16(uint32_t dst, const void* src) {
    asm volatile("cp.async.cg.shared.global [%0], [%1], 16;" :: "r"(dst), "l"(src));
}
__device__ __forceinline__ void mma16816(float* c, const uint32_t* a, const uint32_t* b) {
    asm volatile(
        "mma.sync.aligned.m16n8k16.row.col.f32.bf16.bf16.f32 "
        "{%0,%1,%2,%3}, {%4,%5,%6,%7}, {%8,%9}, {%0,%1,%2,%3};"
        : "+f"(c[0]), "+f"(c[1]), "+f"(c[2]), "+f"(c[3])
        : "r"(a[0]), "r"(a[1]), "r"(a[2]), "r"(a[3]), "r"(b[0]), "r"(b[1]));
}
__device__ __forceinline__ void mma16816h(float* c, const uint32_t* a, const uint32_t* b) {
    asm volatile(
        "mma.sync.aligned.m16n8k16.row.col.f32.f16.f16.f32 "
        "{%0,%1,%2,%3}, {%4,%5,%6,%7}, {%8,%9}, {%0,%1,%2,%3};"
        : "+f"(c[0]), "+f"(c[1]), "+f"(c[2]), "+f"(c[3])
        : "r"(a[0]), "r"(a[1]), "r"(a[2]), "r"(a[3]), "r"(b[0]), "r"(b[1]));
}
__device__ __forceinline__ void split2(float a, float b, uint32_t& hi, uint32_t& lo) {
    __nv_bfloat16 h0 = __float2bfloat16_rn(a), h1 = __float2bfloat16_rn(b);
    __nv_bfloat16 l0 = __float2bfloat16_rn(a - __bfloat162float(h0));
    __nv_bfloat16 l1 = __float2bfloat16_rn(b - __bfloat162float(h1));
    hi = (uint32_t)__bfloat16_as_ushort(h0) | ((uint32_t)__bfloat16_as_ushort(h1) << 16);
    lo = (uint32_t)__bfloat16_as_ushort(l0) | ((uint32_t)__bfloat16_as_ushort(l1) << 16);
}
__device__ __forceinline__ uint32_t packh2(float a, float b) {
    __half2 h = __floats2half2_rn(a, b);
    return *(uint32_t*)&h;
}

// ---- GEMM params --------------------------------------------------------------
struct GemmP {
    int nk, ldA, ldB, zshift, zmask;
    int aZ1, aZ2, aConst;
    int bZ1, bZ2, bConst;
    long long cZ1, cZ2;
    int ldC, biasMode, outMode;
    const float* bias;
    float* Cf;
    __nv_bfloat16* Chi; __nv_bfloat16* Clo;
    float alpha;
    int k0 = 0;      // K element offset (split-K)
};

// ---- bf16 3-term GEMM: 128x128x32, 128 thr, 2 stages, 2 CTAs/SM ---------------
__global__ void __launch_bounds__(128, 2)
hmma_gemm(const __nv_bfloat16* __restrict__ Ahg, const __nv_bfloat16* __restrict__ Alg,
          const __nv_bfloat16* __restrict__ Bhg, const __nv_bfloat16* __restrict__ Blg,
          const GemmP p)
{
    extern __shared__ __align__(16) __nv_bfloat16 sm[];
    const int tid = threadIdx.x, lane = tid & 31, wid = tid >> 5;
    const int wm = (wid >> 1) * 64, wn = (wid & 1) * 64;
    const int zh = blockIdx.z >> p.zshift, zl = blockIdx.z & p.zmask;
    const long long arow0 = (long long)p.aZ1 * zh + p.aZ2 * zl + p.aConst
                            + (long long)blockIdx.y * 128;
    const long long brow0 = (long long)p.bZ1 * zh + p.bZ2 * zl + p.bConst
                            + (long long)blockIdx.x * 128;
    const __nv_bfloat16* gAh = Ahg + arow0 * p.ldA;
    const __nv_bfloat16* gAl = Alg + arow0 * p.ldA;
    const __nv_bfloat16* gBh = Bhg + brow0 * p.ldB;
    const __nv_bfloat16* gBl = Blg + brow0 * p.ldB;
    const uint32_t smbase = smem_u32(sm);
    const int ldA = p.ldA, ldB = p.ldB, nk = p.nk, k0 = p.k0;

    auto load_stage = [&](int st, int kb) {
        const uint32_t sb = smbase + (uint32_t)st * STG2_BYTES;
        const long long koff = (long long)kb * BKB + k0;
#pragma unroll
        for (int i = 0; i < 4; i++) {
            const int c = tid + i * 128;       // 0..511 (128 rows x 4 chunks)
            const int row = c >> 2, ch = c & 3;
            const uint32_t doff = (uint32_t)(row * PADK2 + ch * 8) * 2;
            const long long ga = (long long)row * ldA + koff + ch * 8;
            const long long gb = (long long)row * ldB + koff + ch * 8;
            cpasync16(sb + doff, gAh + ga);
            cpasync16(sb + OFF2_AL + doff, gAl + ga);
            cpasync16(sb + OFF2_BH + doff, gBh + gb);
            cpasync16(sb + OFF2_BL + doff, gBl + gb);
        }
        asm volatile("cp.async.commit_group;" ::: "memory");
    };

    load_stage(0, 0);
    load_stage(1, 1);

    float acc[4][8][4];
#pragma unroll
    for (int a = 0; a < 4; a++)
#pragma unroll
        for (int b = 0; b < 8; b++)
#pragma unroll
            for (int c = 0; c < 4; c++) acc[a][b][c] = 0.0f;

    const int krow = (lane & 3) * 2;
    const int grow = lane >> 2;

    for (int kb = 0; kb < nk; kb++) {
        asm volatile("cp.async.wait_group 1;" ::: "memory");
        __syncthreads();
        const int st = kb & 1;
        const __nv_bfloat16* sAh = sm + (size_t)st * STG2_ELT;
        const __nv_bfloat16* sAl = sAh + T2_ELT;
        const __nv_bfloat16* sBh = sAl + T2_ELT;
        const __nv_bfloat16* sBl = sBh + T2_ELT;

#pragma unroll
        for (int k16 = 0; k16 < 2; k16++) {
            const int kk = k16 * 16 + krow;
            uint32_t ah[4][4], al[4][4];
#pragma unroll
            for (int mt = 0; mt < 4; mt++) {
                const int r0 = (wm + mt * 16 + grow) * PADK2;
                const int r1 = r0 + 8 * PADK2;
                ah[mt][0] = *(const uint32_t*)(sAh + r0 + kk);
                ah[mt][1] = *(const uint32_t*)(sAh + r1 + kk);
                ah[mt][2] = *(const uint32_t*)(sAh + r0 + kk + 8);
                ah[mt][3] = *(const uint32_t*)(sAh + r1 + kk + 8);
                al[mt][0] = *(const uint32_t*)(sAl + r0 + kk);
                al[mt][1] = *(const uint32_t*)(sAl + r1 + kk);
                al[mt][2] = *(const uint32_t*)(sAl + r0 + kk + 8);
                al[mt][3] = *(const uint32_t*)(sAl + r1 + kk + 8);
            }
#pragma unroll
            for (int nt = 0; nt < 8; nt++) {
                const int r = (wn + nt * 8 + grow) * PADK2;
                uint32_t bh[2], bl[2];
                bh[0] = *(const uint32_t*)(sBh + r + kk);
                bh[1] = *(const uint32_t*)(sBh + r + kk + 8);
                bl[0] = *(const uint32_t*)(sBl + r + kk);
                bl[1] = *(const uint32_t*)(sBl + r + kk + 8);
#pragma unroll
                for (int mt = 0; mt < 4; mt++)
                    mma16816(acc[mt][nt], ah[mt], bh);
#pragma unroll
                for (int mt = 0; mt < 4; mt++)
                    mma16816(acc[mt][nt], ah[mt], bl);
#pragma unroll
                for (int mt = 0; mt < 4; mt++)
                    mma16816(acc[mt][nt], al[mt], bh);
            }
        }
        __syncthreads();
        if (kb + 2 < nk) load_stage(st, kb + 2);
    }

    const long long cbase = p.cZ1 * zh + p.cZ2 * zl;
    const int n0 = blockIdx.x * 128 + wn + (lane & 3) * 2;
    const int m0 = blockIdx.y * 128 + wm + (lane >> 2);
#pragma unroll
    for (int mt = 0; mt < 4; mt++) {
#pragma unroll
        for (int half = 0; half < 2; half++) {
            const int m = m0 + mt * 16 + half * 8;
            const float bm = (p.biasMode == 1) ? p.bias[m] : 0.0f;
            const long long rowoff = cbase + (long long)m * p.ldC;
#pragma unroll
            for (int nt = 0; nt < 8; nt++) {
                const int n = n0 + nt * 8;
                float v0 = acc[mt][nt][half * 2 + 0] * p.alpha + bm;
                float v1 = acc[mt][nt][half * 2 + 1] * p.alpha + bm;
                if (p.biasMode == 2) { v0 += p.bias[n]; v1 += p.bias[n + 1]; }
                if (p.outMode == 0) {
                    *(float2*)(p.Cf + rowoff + n) = make_float2(v0, v1);
                } else {
                    uint32_t h, l;
                    split2(v0, v1, h, l);
                    *(uint32_t*)(p.Chi + rowoff + n) = h;
                    *(uint32_t*)(p.Clo + rowoff + n) = l;
                }
            }
        }
    }
}

// ---- fp16 1-term GEMM: 128x128x64 tile, 4 warps, 3 stages, 2 CTAs/SM -----------
__global__ void __launch_bounds__(128, 2)
hmma_gemm_f16(const __half* __restrict__ Ag, const __half* __restrict__ Bg,
              const GemmP p)
{
    extern __shared__ __align__(16) __half smh[];
    const int tid = threadIdx.x, lane = tid & 31, wid = tid >> 5;
    const int wm = (wid >> 1) * 64, wn = (wid & 1) * 64;
    const int zh = blockIdx.z >> p.zshift, zl = blockIdx.z & p.zmask;
    const long long arow0 = (long long)p.aZ1 * zh + p.aZ2 * zl + p.aConst
                            + (long long)blockIdx.y * 128;
    const long long brow0 = (long long)p.bZ1 * zh + p.bZ2 * zl + p.bConst
                            + (long long)blockIdx.x * 128;
    const __half* gA = Ag + arow0 * p.ldA;
    const __half* gB = Bg + brow0 * p.ldB;
    const uint32_t smbase = smem_u32(smh);
    const int ldA = p.ldA, ldB = p.ldB, nk = p.nk;

    auto load_stage = [&](int st, int kb) {
        const uint32_t sb = smbase + (uint32_t)st * STG_BYTES_H;
        const long long koff = (long long)kb * 64;
#pragma unroll
        for (int i = 0; i < 8; i++) {
            const int c = tid + i * 128;
            const int row = c >> 3, ch = c & 7;
            const uint32_t doff = (uint32_t)(row * PADK + ch * 8) * 2;
            cpasync16(sb + doff, gA + (long long)row * ldA + koff + ch * 8);
            cpasync16(sb + OFF_B_H + doff, gB + (long long)row * ldB + koff + ch * 8);
        }
        asm volatile("cp.async.commit_group;" ::: "memory");
    };

    load_stage(0, 0);
    load_stage(1, 1);
    load_stage(2, 2);

    float acc[4][8][4];
#pragma unroll
    for (int a = 0; a < 4; a++)
#pragma unroll
        for (int b = 0; b < 8; b++)
#pragma unroll
            for (int c = 0; c < 4; c++) acc[a][b][c] = 0.0f;

    const int krow = (lane & 3) * 2;
    const int grow = lane >> 2;

    for (int kb = 0; kb < nk; kb++) {
        asm volatile("cp.async.wait_group 2;" ::: "memory");
        __syncthreads();
        const int st = kb % 3;
        const __half* sA = smh + (size_t)st * STG_ELT_H;
        const __half* sB = sA + AH_TILE_ELT;

#pragma unroll
        for (int k16 = 0; k16 < 4; k16++) {
            const int kk = k16 * 16 + krow;
            uint32_t ah[4][4];
#pragma unroll
            for (int mt = 0; mt < 4; mt++) {
                const int r0 = (wm + mt * 16 + grow) * PADK;
                const int r1 = r0 + 8 * PADK;
                ah[mt][0] = *(const uint32_t*)(sA + r0 + kk);
                ah[mt][1] = *(const uint32_t*)(sA + r1 + kk);
                ah[mt][2] = *(const uint32_t*)(sA + r0 + kk + 8);
                ah[mt][3] = *(const uint32_t*)(sA + r1 + kk + 8);
            }
#pragma unroll
            for (int nt = 0; nt < 8; nt++) {
                const int r = (wn + nt * 8 + grow) * PADK;
                uint32_t bh[2];
                bh[0] = *(const uint32_t*)(sB + r + kk);
                bh[1] = *(const uint32_t*)(sB + r + kk + 8);
#pragma unroll
                for (int mt = 0; mt < 4; mt++)
                    mma16816h(acc[mt][nt], ah[mt], bh);
            }
        }
        __syncthreads();
        if (kb + 3 < nk) load_stage(st, kb + 3);
    }

    const long long cbase = p.cZ1 * zh + p.cZ2 * zl;
    const int n0 = blockIdx.x * 128 + wn + (lane & 3) * 2;
    const int m0 = blockIdx.y * 128 + wm + (lane >> 2);
    __half* Ch = (__half*)p.Chi;
#pragma unroll
    for (int mt = 0; mt < 4; mt++) {
#pragma unroll
        for (int half = 0; half < 2; half++) {
            const int m = m0 + mt * 16 + half * 8;
            const float bm = (p.biasMode == 1) ? p.bias[m] : 0.0f;
            const long long rowoff = cbase + (long long)m * p.ldC;
#pragma unroll
            for (int nt = 0; nt < 8; nt++) {
                const int n = n0 + nt * 8;
                float v0 = acc[mt][nt][half * 2 + 0] * p.alpha + bm;
                float v1 = acc[mt][nt][half * 2 + 1] * p.alpha + bm;
                if (p.biasMode == 2) { v0 += p.bias[n]; v1 += p.bias[n + 1]; }
                if (p.outMode == 0) {
                    *(float2*)(p.Cf + rowoff + n) = make_float2(v0, v1);
                } else {
                    *(uint32_t*)(Ch + rowoff + n) = packh2(v0, v1);
                }
            }
        }
    }
}

// ---- conversions -------------------------------------------------------------
__global__ void split_kernel(const float4* __restrict__ in, uint2* __restrict__ hi,
                             uint2* __restrict__ lo, int n4)
{
    int i = blockIdx.x * 256 + threadIdx.x;
    if (i >= n4) return;
    float4 v = in[i];
    uint32_t h0, l0, h1, l1;
    split2(v.x, v.y, h0, l0);
    split2(v.z, v.w, h1, l1);
    hi[i] = make_uint2(h0, h1);
    lo[i] = make_uint2(l0, l1);
}

__global__ void half_kernel(const float4* __restrict__ in, uint2* __restrict__ out,
                            int n4)
{
    int i = blockIdx.x * 256 + threadIdx.x;
    if (i >= n4) return;
    float4 v = in[i];
    out[i] = make_uint2(packh2(v.x, v.y), packh2(v.z, v.w));
}

__global__ void transpose_split_kernel(const float* __restrict__ x,
                                       __nv_bfloat16* __restrict__ hi,
                                       __nv_bfloat16* __restrict__ lo,
                                       __half* __restrict__ hf)
{
    __shared__ float tile[32][33];
    const int b = blockIdx.z;
    const int c0 = blockIdx.y * 32, n0 = blockIdx.x * 32;
    const int tx = threadIdx.x, ty = threadIdx.y;
    const float* xb = x + (long long)b * 16777216;
#pragma unroll
    for (int i = 0; i < 4; i++)
        tile[ty + i * 8][tx] = xb[(long long)(c0 + ty + i * 8) * 4096 + n0 + tx];
    __syncthreads();
#pragma unroll
    for (int i = 0; i < 4; i++) {
        float v = tile[tx][ty + i * 8];
        __nv_bfloat16 h = __float2bfloat16_rn(v);
        __nv_bfloat16 l = __float2bfloat16_rn(v - __bfloat162float(h));
        long long o = (long long)b * 16777216 + (long long)(n0 + ty + i * 8) * 4096 + c0 + tx;
        hi[o] = h; lo[o] = l; hf[o] = __float2half_rn(v);
    }
}

__global__ void transpose_split2_kernel(const float* __restrict__ w,
                                        __nv_bfloat16* __restrict__ hi,
                                        __nv_bfloat16* __restrict__ lo)
{
    __shared__ float tile[32][33];
    const int m0 = blockIdx.y * 32, n0 = blockIdx.x * 32;
    const int tx = threadIdx.x, ty = threadIdx.y;
#pragma unroll
    for (int i = 0; i < 4; i++)
        tile[ty + i * 8][tx] = w[(long long)(m0 + ty + i * 8) * 4096 + n0 + tx];
    __syncthreads();
#pragma unroll
    for (int i = 0; i < 4; i++) {
        float v = tile[tx][ty + i * 8];
        __nv_bfloat16 h = __float2bfloat16_rn(v);
        __nv_bfloat16 l = __float2bfloat16_rn(v - __bfloat162float(h));
        long long o = (long long)(n0 + ty + i * 8) * 4096 + m0 + tx;
        hi[o] = h; lo[o] = l;
    }
}

__global__ void wvec_kernel(const float* __restrict__ Wk,
                            const float* __restrict__ bq,
                            float* __restrict__ w)
{
    const int n = blockIdx.x * 256 + threadIdx.x;
    float acc = 0.0f;
    for (int m = 0; m < 4096; m++)
        acc += Wk[(long long)m * 4096 + n] * bq[m];
    w[n] = acc;
}

__global__ void beta_kernel(const __nv_bfloat16* __restrict__ qkv_h,
                            const __nv_bfloat16* __restrict__ qkv_l,
                            const float* __restrict__ w,
                            float* __restrict__ beta)
{
    const int bb = blockIdx.x;
    const int z = bb >> 9, d = bb & 511;
    const int b = z >> 3, h = z & 7;
    const long long row = (long long)(b * 8192 + 4096 + h * 512 + d) * 4096;
    __shared__ float red[256];
    const int t = threadIdx.x;
    float acc = 0.0f;
    for (int n = t; n < 4096; n += 256)
        acc += w[n] * (__bfloat162float(qkv_h[row + n]) + __bfloat162float(qkv_l[row + n]));
    red[t] = acc; __syncthreads();
#pragma unroll
    for (int s = 128; s > 0; s >>= 1) {
        if (t < s) red[t] += red[t + s];
        __syncthreads();
    }
    if (t == 0) beta[bb] = 0.125f * red[0];
}

__global__ void softmax_f16_kernel(const float* __restrict__ dot,
                                   const float* __restrict__ dot2,
                                   const float* __restrict__ beta,
                                   __half* __restrict__ attn)
{
    const long long row = blockIdx.x;
    const float* p = dot + row * 512;
    const float* p2 = dot2 + row * 512;
    const float* bb = beta + ((row >> 9) << 9);
    __shared__ float red[256];
    const int t = threadIdx.x;
    float v0 = p[t] + p2[t] + bb[t];
    float v1 = p[t + 256] + p2[t + 256] + bb[t + 256];
    red[t] = fmaxf(v0, v1); __syncthreads();
#pragma unroll
    for (int s = 128; s > 0; s >>= 1) {
        if (t < s) red[t] = fmaxf(red[t], red[t + s]);
        __syncthreads();
    }
    float mx = red[0]; __syncthreads();
    float e0 = expf(v0 - mx), e1 = expf(v1 - mx);
    red[t] = e0 + e1; __syncthreads();
#pragma unroll
    for (int s = 128; s > 0; s >>= 1) {
        if (t < s) red[t] += red[t + s];
        __syncthreads();
    }
    float inv = 1.0f / red[0];
    attn[row * 512 + t]       = __float2half_rn(e0 * inv);
    attn[row * 512 + t + 256] = __float2half_rn(e1 * inv);
}

// ---- host --------------------------------------------------------------------
extern "C" void kernel_launch(void* const* d_in, const int* in_sizes, int n_in,
                              void* d_out, int out_size)
{
    const float* x    = (const float*)d_in[0];
    const float* Wqkv = (const float*)d_in[1];
    const float* bqkv = (const float*)d_in[2];
    const float* Wq   = (const float*)d_in[3];
    const float* bq   = (const float*)d_in[4];
    const float* Wk   = (const float*)d_in[5];
    const float* bk   = (const float*)d_in[6];
    const float* Wv   = (const float*)d_in[7];
    const float* bv   = (const float*)d_in[8];
    const float* Wout = (const float*)d_in[9];
    const float* bout = (const float*)d_in[10];
    float* y = (float*)d_out;
    (void)bk;

    __nv_bfloat16 *xT_h, *xT_l, *Wqkv_h, *Wqkv_l, *WqT_h, *WqT_l, *WkT_h, *WkT_l,
        *qkv_h, *qkv_l, *q2_h, *q2_l, *H_h, *H_l;
    __half *xT_f, *Wqkv_vf, *Wv_f, *Wout_f, *v_f, *v2T_f, *attn_f, *outT_f;
    float *dot, *dot2, *wvec, *beta;
    cudaGetSymbolAddress((void**)&xT_h,   g_xT_hi);   cudaGetSymbolAddress((void**)&xT_l,   g_xT_lo);
    cudaGetSymbolAddress((void**)&xT_f,   g_xT_f);
    cudaGetSymbolAddress((void**)&Wqkv_h, g_Wqkv_hi); cudaGetSymbolAddress((void**)&Wqkv_l, g_Wqkv_lo);
    cudaGetSymbolAddress((void**)&Wqkv_vf,g_Wqkv_vf);
    cudaGetSymbolAddress((void**)&WqT_h,  g_WqT_hi);  cudaGetSymbolAddress((void**)&WqT_l,  g_WqT_lo);
    cudaGetSymbolAddress((void**)&WkT_h,  g_WkT_hi);  cudaGetSymbolAddress((void**)&WkT_l,  g_WkT_lo);
    cudaGetSymbolAddress((void**)&Wv_f,   g_Wv_f);    cudaGetSymbolAddress((void**)&Wout_f, g_Wout_f);
    cudaGetSymbolAddress((void**)&qkv_h,  g_qkv_hi);  cudaGetSymbolAddress((void**)&qkv_l,  g_qkv_lo);
    cudaGetSymbolAddress((void**)&v_f,    g_v_f);
    cudaGetSymbolAddress((void**)&q2_h,   g_q2_hi);   cudaGetSymbolAddress((void**)&q2_l,   g_q2_lo);
    cudaGetSymbolAddress((void**)&H_h,    g_H_hi);    cudaGetSymbolAddress((void**)&H_l,    g_H_lo);
    cudaGetSymbolAddress((void**)&v2T_f,  g_v2T_f);
    cudaGetSymbolAddress((void**)&attn_f, g_attn_f);
    cudaGetSymbolAddress((void**)&outT_f, g_outT_f);
    cudaGetSymbolAddress((void**)&dot,    g_dot);
    cudaGetSymbolAddress((void**)&dot2,   g_dot2);
    cudaGetSymbolAddress((void**)&wvec,   g_wvec);
    cudaGetSymbolAddress((void**)&beta,   g_beta);

    cudaFuncSetAttribute(hmma_gemm, cudaFuncAttributeMaxDynamicSharedMemorySize, SMEM_REQ2);
    cudaFuncSetAttribute(hmma_gemm_f16, cudaFuncAttributeMaxDynamicSharedMemorySize, SMEM_REQ_H);

    static cudaStream_t s1 = nullptr;
    static cudaEvent_t e0, e1, eqk, eqg, eb, el2;
    if (!s1) {
        cudaStreamCreateWithFlags(&s1, cudaStreamNonBlocking);
        cudaEventCreateWithFlags(&e0,  cudaEventDisableTiming);
        cudaEventCreateWithFlags(&e1,  cudaEventDisableTiming);
        cudaEventCreateWithFlags(&eqk, cudaEventDisableTiming);
        cudaEventCreateWithFlags(&eqg, cudaEventDisableTiming);
        cudaEventCreateWithFlags(&eb,  cudaEventDisableTiming);
        cudaEventCreateWithFlags(&el2, cudaEventDisableTiming);
    }

    GemmP p;

    // ---- main stream: x conversion, Wqkv split, big q/k GEMM ----
    transpose_split_kernel<<<dim3(128, 128, 2), dim3(32, 8)>>>(x, xT_h, xT_l, xT_f);
    cudaEventRecord(e0, 0);
    split_kernel<<<32768, 256>>>((const float4*)Wqkv, (uint2*)Wqkv_h, (uint2*)Wqkv_l, 8388608);
    // Stage 1qk: qkv_qk[b] = Wqkv[0:8192] @ xT[b]^T + bqkv
    p = {128, 4096, 4096, 0, 0,  0, 0, 0,  4096, 0, 0,  33554432LL, 0,
         4096, 1, 1, bqkv, nullptr, qkv_h, qkv_l, 1.0f};
    hmma_gemm<<<dim3(32, 64, 2), 128, SMEM_REQ2>>>(Wqkv_h, Wqkv_l, xT_h, xT_l, p);
    cudaEventRecord(eqk, 0);

    // ---- side stream: weight conversions, H, fp16 v-chain ----
    transpose_split2_kernel<<<dim3(128, 128, 1), dim3(32, 8), 0, s1>>>(Wq, WqT_h, WqT_l);
    transpose_split2_kernel<<<dim3(128, 128, 1), dim3(32, 8), 0, s1>>>(Wk, WkT_h, WkT_l);
    half_kernel<<<16384, 256, 0, s1>>>((const float4*)Wv,   (uint2*)Wv_f,   4194304);
    half_kernel<<<16384, 256, 0, s1>>>((const float4*)Wout, (uint2*)Wout_f, 4194304);
    half_kernel<<<16384, 256, 0, s1>>>((const float4*)(Wqkv + 33554432LL), (uint2*)Wqkv_vf, 4194304);
    wvec_kernel<<<16, 256, 0, s1>>>(Wk, bq, wvec);
    // H = Wk^T Wq (once)
    p = {128, 4096, 4096, 0, 0,  0, 0, 0,  0, 0, 0,  0LL, 0LL,
         4096, 0, 1, nullptr, nullptr, H_h, H_l, 1.0f};
    hmma_gemm<<<dim3(32, 32, 1), 128, SMEM_REQ2, s1>>>(WkT_h, WkT_l, WqT_h, WqT_l, p);
    cudaStreamWaitEvent(s1, e0, 0);
    // Stage 1v (fp16)
    p = {64, 4096, 4096, 0, 0,  0, 0, 0,  4096, 0, 0,  16777216LL, 0,
         4096, 1, 2, bqkv + 8192, nullptr, (__nv_bfloat16*)v_f, nullptr, 1.0f};
    hmma_gemm_f16<<<dim3(32, 32, 2), 128, SMEM_REQ_H, s1>>>(Wqkv_vf, xT_f, p);
    // Stage 2v (fp16, transposed)
    p = {64, 4096, 4096, 3, 7,  0, 0, 0,  4096, 512, 0,  16777216LL, 2097152LL,
         512, 1, 2, bv, nullptr, (__nv_bfloat16*)v2T_f, nullptr, 1.0f};
    hmma_gemm_f16<<<dim3(4, 32, 16), 128, SMEM_REQ_H, s1>>>(Wv_f, v_f, p);
    cudaEventRecord(e1, s1);
    cudaStreamWaitEvent(s1, eqk, 0);
    beta_kernel<<<8192, 256, 0, s1>>>(qkv_h, qkv_l, wvec, beta);
    cudaEventRecord(eb, s1);

    // ---- main: qG, logits (split-K), softmax, out ----
    cudaStreamWaitEvent(0, e1, 0);
    p = {128, 4096, 4096, 3, 7,  8192, 512, 0,  0, 0, 0,  16777216LL, 2097152LL,
         4096, 0, 1, nullptr, nullptr, q2_h, q2_l, 1.0f};
    hmma_gemm<<<dim3(32, 4, 16), 128, SMEM_REQ2>>>(qkv_h, qkv_l, H_h, H_l, p);
    cudaEventRecord(eqg, 0);

    // logits half 2 on s1 (K = 2048..4095)
    cudaStreamWaitEvent(s1, eqg, 0);
    p = {64, 4096, 4096, 3, 7,  4096, 512, 0,  8192, 512, 4096,  2097152LL, 262144LL,
         512, 0, 0, nullptr, dot2, nullptr, nullptr, 0.125f};
    p.k0 = 2048;
    hmma_gemm<<<dim3(4, 4, 16), 128, SMEM_REQ2, s1>>>(q2_h, q2_l, qkv_h, qkv_l, p);
    cudaEventRecord(el2, s1);

    // logits half 1 on main (K = 0..2047)
    p = {64, 4096, 4096, 3, 7,  4096, 512, 0,  8192, 512, 4096,  2097152LL, 262144LL,
         512, 0, 0, nullptr, dot, nullptr, nullptr, 0.125f};
    hmma_gemm<<<dim3(4, 4, 16), 128, SMEM_REQ2>>>(q2_h, q2_l, qkv_h, qkv_l, p);

    cudaStreamWaitEvent(0, eb, 0);
    cudaStreamWaitEvent(0, el2, 0);
    softmax_f16_kernel<<<8192, 256>>>(dot, dot2, beta, attn_f);

    // Stage 5 (fp16, transposed)
    p = {8, 512, 512, 3, 7,  32768, 4096, 0,  4096, 512, 0,  16777216LL, 512LL,
         4096, 0, 2, nullptr, nullptr, (__nv_bfloat16*)outT_f, nullptr, 1.0f};
    hmma_gemm_f16<<<dim3(4, 32, 16), 128, SMEM_REQ_H>>>(v2T_f, attn_f, p);

    // Stage 6 (fp16): y = Wout @ outT^T + bout
    p = {64, 4096, 4096, 0, 0,  0, 0, 0,  4096, 0, 0,  16777216LL, 0,
         4096, 1, 0, bout, y, nullptr, nullptr, 1.0f};
    hmma_gemm_f16<<<dim3(32, 32, 2), 128, SMEM_REQ_H>>>(Wout_f, outT_f, p);

    (void)in_sizes; (void)n_in; (void)out_size;
}

// round 17
// speedup vs baseline: 1.0461x; 1.0461x over previous
#include <cuda_runtime.h>
#include <cuda_bf16.h>
#include <cuda_fp16.h>
#include <cstdint>

// ============================================================================
// Mixed-precision HMMA pipeline. All GEMMs NT: D[m][n] = sum_k A[m][k]B[n][k].
//  - Pre-softmax path: split-bf16 3-term, fp32 accum. 256x128x64 tile, 1 CTA/SM.
//  - v-chain + post-softmax: fp16 1-term. 128x128x64 tile, 3-stage, 2 CTA/SM.
// Logit path via associativity: logits ~ 0.125*(qkv_q.H.qkv_k^T) + 0.125*beta
//   H = Wk^T Wq (once), beta[d] = (Wk^T bq) . qkv_k[d,:]
// Dual-stream fork-join schedule + split-K x2 logits.
// R16: s1 forks from capture root; Wqkv split is s1's first captured op
//      (overlaps x-transpose inside the graph). All waits are in-capture.
// ============================================================================

#define PADK 72
#define A_TILE_ELT (256 * PADK)
#define B_TILE_ELT (128 * PADK)
#define STG_ELT (2 * A_TILE_ELT + 2 * B_TILE_ELT)
#define STG_BYTES (STG_ELT * 2)
#define SMEM_REQ (2 * STG_BYTES)
#define OFF_AL (A_TILE_ELT * 2)
#define OFF_BH (2 * A_TILE_ELT * 2)
#define OFF_BL (2 * A_TILE_ELT * 2 + B_TILE_ELT * 2)

#define AH_TILE_ELT (128 * PADK)
#define STG_ELT_H (2 * AH_TILE_ELT)
#define STG_BYTES_H (STG_ELT_H * 2)
#define SMEM_REQ_H (3 * STG_BYTES_H)
#define OFF_B_H (AH_TILE_ELT * 2)

// ---- scratch (device globals) ----------------------------------------------
__device__ __align__(256) __nv_bfloat16 g_xT_hi[33554432],  g_xT_lo[33554432];
__device__ __align__(256) __half        g_xT_f[33554432];
__device__ __align__(256) __nv_bfloat16 g_Wqkv_hi[33554432],g_Wqkv_lo[33554432];
__device__ __align__(256) __half        g_Wqkv_vf[16777216];
__device__ __align__(256) __nv_bfloat16 g_WqT_hi[16777216], g_WqT_lo[16777216];
__device__ __align__(256) __nv_bfloat16 g_WkT_hi[16777216], g_WkT_lo[16777216];
__device__ __align__(256) __half        g_Wv_f[16777216],   g_Wout_f[16777216];
__device__ __align__(256) __nv_bfloat16 g_qkv_hi[67108864], g_qkv_lo[67108864];
__device__ __align__(256) __half        g_v_f[33554432];
__device__ __align__(256) __nv_bfloat16 g_q2_hi[33554432],  g_q2_lo[33554432];
__device__ __align__(256) __nv_bfloat16 g_H_hi[16777216],   g_H_lo[16777216];
__device__ __align__(256) __half        g_v2T_f[33554432];
__device__ __align__(256) __half        g_attn_f[4194304];
__device__ __align__(256) __half        g_outT_f[33554432];
__device__ __align__(256) float g_dot[4194304];
__device__ __align__(256) float g_dot2[4194304];
__device__ __align__(256) float g_wvec[4096];
__device__ __align__(256) float g_beta[8192];

// ---- helpers ----------------------------------------------------------------
__device__ __forceinline__ uint32_t smem_u32(const void* p) {
    uint32_t r;
    asm("{ .reg .u64 t; cvta.to.shared.u64 t, %1; cvt.u32.u64 %0, t; }" : "=r"(r) : "l"(p));
    return r;
}
__device__ __forceinline__ void cpasync16(uint32_t dst, const void* src) {
    asm volatile("cp.async.cg.shared.global [%0], [%1], 16;" :: "r"(dst), "l"(src));
}
__device__ __forceinline__ void mma16816(float* c, const uint32_t* a, const uint32_t* b) {
    asm volatile(
        "mma.sync.aligned.m16n8k16.row.col.f32.bf16.bf16.f32 "
        "{%0,%1,%2,%3}, {%4,%5,%6,%7}, {%8,%9}, {%0,%1,%2,%3};"
        : "+f"(c[0]), "+f"(c[1]), "+f"(c[2]), "+f"(c[3])
        : "r"(a[0]), "r"(a[1]), "r"(a[2]), "r"(a[3]), "r"(b[0]), "r"(b[1]));
}
__device__ __forceinline__ void mma16816h(float* c, const uint32_t* a, const uint32_t* b) {
    asm volatile(
        "mma.sync.aligned.m16n8k16.row.col.f32.f16.f16.f32 "
        "{%0,%1,%2,%3}, {%4,%5,%6,%7}, {%8,%9}, {%0,%1,%2,%3};"
        : "+f"(c[0]), "+f"(c[1]), "+f"(c[2]), "+f"(c[3])
        : "r"(a[0]), "r"(a[1]), "r"(a[2]), "r"(a[3]), "r"(b[0]), "r"(b[1]));
}
__device__ __forceinline__ void split2(float a, float b, uint32_t& hi, uint32_t& lo) {
    __nv_bfloat16 h0 = __float2bfloat16_rn(a), h1 = __float2bfloat16_rn(b);
    __nv_bfloat16 l0 = __float2bfloat16_rn(a - __bfloat162float(h0));
    __nv_bfloat16 l1 = __float2bfloat16_rn(b - __bfloat162float(h1));
    hi = (uint32_t)__bfloat16_as_ushort(h0) | ((uint32_t)__bfloat16_as_ushort(h1) << 16);
    lo = (uint32_t)__bfloat16_as_ushort(l0) | ((uint32_t)__bfloat16_as_ushort(l1) << 16);
}
__device__ __forceinline__ uint32_t packh2(float a, float b) {
    __half2 h = __floats2half2_rn(a, b);
    return *(uint32_t*)&h;
}

// ---- GEMM params --------------------------------------------------------------
struct GemmP {
    int nk, ldA, ldB, zshift, zmask;
    int aZ1, aZ2, aConst;
    int bZ1, bZ2, bConst;
    long long cZ1, cZ2;
    int ldC, biasMode, outMode;
    const float* bias;
    float* Cf;
    __nv_bfloat16* Chi; __nv_bfloat16* Clo;
    float alpha;
    int k0 = 0;      // K element offset (split-K)
};

// ---- bf16 3-term GEMM: 256x128x64, 256 thr, 2 stages (R13-proven) -------------
__global__ void __launch_bounds__(256, 1)
hmma_gemm(const __nv_bfloat16* __restrict__ Ahg, const __nv_bfloat16* __restrict__ Alg,
          const __nv_bfloat16* __restrict__ Bhg, const __nv_bfloat16* __restrict__ Blg,
          const GemmP p)
{
    extern __shared__ __align__(16) __nv_bfloat16 sm[];
    const int tid = threadIdx.x, lane = tid & 31, wid = tid >> 5;
    const int wm = (wid >> 1) * 64, wn = (wid & 1) * 64;
    const int zh = blockIdx.z >> p.zshift, zl = blockIdx.z & p.zmask;
    const long long arow0 = (long long)p.aZ1 * zh + p.aZ2 * zl + p.aConst
                            + (long long)blockIdx.y * 256;
    const long long brow0 = (long long)p.bZ1 * zh + p.bZ2 * zl + p.bConst
                            + (long long)blockIdx.x * 128;
    const __nv_bfloat16* gAh = Ahg + arow0 * p.ldA;
    const __nv_bfloat16* gAl = Alg + arow0 * p.ldA;
    const __nv_bfloat16* gBh = Bhg + brow0 * p.ldB;
    const __nv_bfloat16* gBl = Blg + brow0 * p.ldB;
    const uint32_t smbase = smem_u32(sm);
    const int ldA = p.ldA, ldB = p.ldB, nk = p.nk, k0 = p.k0;

    auto load_stage = [&](int st, int kb) {
        const uint32_t sb = smbase + (uint32_t)st * STG_BYTES;
        const long long koff = (long long)kb * 64 + k0;
#pragma unroll
        for (int i = 0; i < 8; i++) {
            const int c = tid + i * 256;
            const int row = c >> 3, ch = c & 7;
            const uint32_t doff = (uint32_t)(row * PADK + ch * 8) * 2;
            const long long ga = (long long)row * ldA + koff + ch * 8;
            cpasync16(sb + doff, gAh + ga);
            cpasync16(sb + OFF_AL + doff, gAl + ga);
        }
#pragma unroll
        for (int i = 0; i < 4; i++) {
            const int c = tid + i * 256;
            const int row = c >> 3, ch = c & 7;
            const uint32_t doff = (uint32_t)(row * PADK + ch * 8) * 2;
            const long long gb = (long long)row * ldB + koff + ch * 8;
            cpasync16(sb + OFF_BH + doff, gBh + gb);
            cpasync16(sb + OFF_BL + doff, gBl + gb);
        }
        asm volatile("cp.async.commit_group;" ::: "memory");
    };

    load_stage(0, 0);
    load_stage(1, 1);

    float acc[4][8][4];
#pragma unroll
    for (int a = 0; a < 4; a++)
#pragma unroll
        for (int b = 0; b < 8; b++)
#pragma unroll
            for (int c = 0; c < 4; c++) acc[a][b][c] = 0.0f;

    const int krow = (lane & 3) * 2;
    const int grow = lane >> 2;

    for (int kb = 0; kb < nk; kb++) {
        asm volatile("cp.async.wait_group 1;" ::: "memory");
        __syncthreads();
        const int st = kb & 1;
        const __nv_bfloat16* sAh = sm + (size_t)st * STG_ELT;
        const __nv_bfloat16* sAl = sAh + A_TILE_ELT;
        const __nv_bfloat16* sBh = sAl + A_TILE_ELT;
        const __nv_bfloat16* sBl = sBh + B_TILE_ELT;

#pragma unroll
        for (int k16 = 0; k16 < 4; k16++) {
            const int kk = k16 * 16 + krow;
            uint32_t ah[4][4], al[4][4];
#pragma unroll
            for (int mt = 0; mt < 4; mt++) {
                const int r0 = (wm + mt * 16 + grow) * PADK;
                const int r1 = r0 + 8 * PADK;
                ah[mt][0] = *(const uint32_t*)(sAh + r0 + kk);
                ah[mt][1] = *(const uint32_t*)(sAh + r1 + kk);
                ah[mt][2] = *(const uint32_t*)(sAh + r0 + kk + 8);
                ah[mt][3] = *(const uint32_t*)(sAh + r1 + kk + 8);
                al[mt][0] = *(const uint32_t*)(sAl + r0 + kk);
                al[mt][1] = *(const uint32_t*)(sAl + r1 + kk);
                al[mt][2] = *(const uint32_t*)(sAl + r0 + kk + 8);
                al[mt][3] = *(const uint32_t*)(sAl + r1 + kk + 8);
            }
#pragma unroll
            for (int nt = 0; nt < 8; nt++) {
                const int r = (wn + nt * 8 + grow) * PADK;
                uint32_t bh[2], bl[2];
                bh[0] = *(const uint32_t*)(sBh + r + kk);
                bh[1] = *(const uint32_t*)(sBh + r + kk + 8);
                bl[0] = *(const uint32_t*)(sBl + r + kk);
                bl[1] = *(const uint32_t*)(sBl + r + kk + 8);
#pragma unroll
                for (int mt = 0; mt < 4; mt++)
                    mma16816(acc[mt][nt], ah[mt], bh);
#pragma unroll
                for (int mt = 0; mt < 4; mt++)
                    mma16816(acc[mt][nt], ah[mt], bl);
#pragma unroll
                for (int mt = 0; mt < 4; mt++)
                    mma16816(acc[mt][nt], al[mt], bh);
            }
        }
        __syncthreads();
        if (kb + 2 < nk) load_stage(st, kb + 2);
    }

    const long long cbase = p.cZ1 * zh + p.cZ2 * zl;
    const int n0 = blockIdx.x * 128 + wn + (lane & 3) * 2;
    const int m0 = blockIdx.y * 256 + wm + (lane >> 2);
#pragma unroll
    for (int mt = 0; mt < 4; mt++) {
#pragma unroll
        for (int half = 0; half < 2; half++) {
            const int m = m0 + mt * 16 + half * 8;
            const float bm = (p.biasMode == 1) ? p.bias[m] : 0.0f;
            const long long rowoff = cbase + (long long)m * p.ldC;
#pragma unroll
            for (int nt = 0; nt < 8; nt++) {
                const int n = n0 + nt * 8;
                float v0 = acc[mt][nt][half * 2 + 0] * p.alpha + bm;
                float v1 = acc[mt][nt][half * 2 + 1] * p.alpha + bm;
                if (p.biasMode == 2) { v0 += p.bias[n]; v1 += p.bias[n + 1]; }
                if (p.outMode == 0) {
                    *(float2*)(p.Cf + rowoff + n) = make_float2(v0, v1);
                } else {
                    uint32_t h, l;
                    split2(v0, v1, h, l);
                    *(uint32_t*)(p.Chi + rowoff + n) = h;
                    *(uint32_t*)(p.Clo + rowoff + n) = l;
                }
            }
        }
    }
}

// ---- fp16 1-term GEMM: 128x128x64 tile, 4 warps, 3 stages, 2 CTAs/SM -----------
__global__ void __launch_bounds__(128, 2)
hmma_gemm_f16(const __half* __restrict__ Ag, const __half* __restrict__ Bg,
              const GemmP p)
{
    extern __shared__ __align__(16) __half smh[];
    const int tid = threadIdx.x, lane = tid & 31, wid = tid >> 5;
    const int wm = (wid >> 1) * 64, wn = (wid & 1) * 64;
    const int zh = blockIdx.z >> p.zshift, zl = blockIdx.z & p.zmask;
    const long long arow0 = (long long)p.aZ1 * zh + p.aZ2 * zl + p.aConst
                            + (long long)blockIdx.y * 128;
    const long long brow0 = (long long)p.bZ1 * zh + p.bZ2 * zl + p.bConst
                            + (long long)blockIdx.x * 128;
    const __half* gA = Ag + arow0 * p.ldA;
    const __half* gB = Bg + brow0 * p.ldB;
    const uint32_t smbase = smem_u32(smh);
    const int ldA = p.ldA, ldB = p.ldB, nk = p.nk;

    auto load_stage = [&](int st, int kb) {
        const uint32_t sb = smbase + (uint32_t)st * STG_BYTES_H;
        const long long koff = (long long)kb * 64;
#pragma unroll
        for (int i = 0; i < 8; i++) {
            const int c = tid + i * 128;
            const int row = c >> 3, ch = c & 7;
            const uint32_t doff = (uint32_t)(row * PADK + ch * 8) * 2;
            cpasync16(sb + doff, gA + (long long)row * ldA + koff + ch * 8);
            cpasync16(sb + OFF_B_H + doff, gB + (long long)row * ldB + koff + ch * 8);
        }
        asm volatile("cp.async.commit_group;" ::: "memory");
    };

    load_stage(0, 0);
    load_stage(1, 1);
    load_stage(2, 2);

    float acc[4][8][4];
#pragma unroll
    for (int a = 0; a < 4; a++)
#pragma unroll
        for (int b = 0; b < 8; b++)
#pragma unroll
            for (int c = 0; c < 4; c++) acc[a][b][c] = 0.0f;

    const int krow = (lane & 3) * 2;
    const int grow = lane >> 2;

    for (int kb = 0; kb < nk; kb++) {
        asm volatile("cp.async.wait_group 2;" ::: "memory");
        __syncthreads();
        const int st = kb % 3;
        const __half* sA = smh + (size_t)st * STG_ELT_H;
        const __half* sB = sA + AH_TILE_ELT;

#pragma unroll
        for (int k16 = 0; k16 < 4; k16++) {
            const int kk = k16 * 16 + krow;
            uint32_t ah[4][4];
#pragma unroll
            for (int mt = 0; mt < 4; mt++) {
                const int r0 = (wm + mt * 16 + grow) * PADK;
                const int r1 = r0 + 8 * PADK;
                ah[mt][0] = *(const uint32_t*)(sA + r0 + kk);
                ah[mt][1] = *(const uint32_t*)(sA + r1 + kk);
                ah[mt][2] = *(const uint32_t*)(sA + r0 + kk + 8);
                ah[mt][3] = *(const uint32_t*)(sA + r1 + kk + 8);
            }
#pragma unroll
            for (int nt = 0; nt < 8; nt++) {
                const int r = (wn + nt * 8 + grow) * PADK;
                uint32_t bh[2];
                bh[0] = *(const uint32_t*)(sB + r + kk);
                bh[1] = *(const uint32_t*)(sB + r + kk + 8);
#pragma unroll
                for (int mt = 0; mt < 4; mt++)
                    mma16816h(acc[mt][nt], ah[mt], bh);
            }
        }
        __syncthreads();
        if (kb + 3 < nk) load_stage(st, kb + 3);
    }

    const long long cbase = p.cZ1 * zh + p.cZ2 * zl;
    const int n0 = blockIdx.x * 128 + wn + (lane & 3) * 2;
    const int m0 = blockIdx.y * 128 + wm + (lane >> 2);
    __half* Ch = (__half*)p.Chi;
#pragma unroll
    for (int mt = 0; mt < 4; mt++) {
#pragma unroll
        for (int half = 0; half < 2; half++) {
            const int m = m0 + mt * 16 + half * 8;
            const float bm = (p.biasMode == 1) ? p.bias[m] : 0.0f;
            const long long rowoff = cbase + (long long)m * p.ldC;
#pragma unroll
            for (int nt = 0; nt < 8; nt++) {
                const int n = n0 + nt * 8;
                float v0 = acc[mt][nt][half * 2 + 0] * p.alpha + bm;
                float v1 = acc[mt][nt][half * 2 + 1] * p.alpha + bm;
                if (p.biasMode == 2) { v0 += p.bias[n]; v1 += p.bias[n + 1]; }
                if (p.outMode == 0) {
                    *(float2*)(p.Cf + rowoff + n) = make_float2(v0, v1);
                } else {
                    *(uint32_t*)(Ch + rowoff + n) = packh2(v0, v1);
                }
            }
        }
    }
}

// ---- conversions -------------------------------------------------------------
__global__ void split_kernel(const float4* __restrict__ in, uint2* __restrict__ hi,
                             uint2* __restrict__ lo, int n4)
{
    int i = blockIdx.x * 256 + threadIdx.x;
    if (i >= n4) return;
    float4 v = in[i];
    uint32_t h0, l0, h1, l1;
    split2(v.x, v.y, h0, l0);
    split2(v.z, v.w, h1, l1);
    hi[i] = make_uint2(h0, h1);
    lo[i] = make_uint2(l0, l1);
}

__global__ void half_kernel(const float4* __restrict__ in, uint2* __restrict__ out,
                            int n4)
{
    int i = blockIdx.x * 256 + threadIdx.x;
    if (i >= n4) return;
    float4 v = in[i];
    out[i] = make_uint2(packh2(v.x, v.y), packh2(v.z, v.w));
}

__global__ void transpose_split_kernel(const float* __restrict__ x,
                                       __nv_bfloat16* __restrict__ hi,
                                       __nv_bfloat16* __restrict__ lo,
                                       __half* __restrict__ hf)
{
    __shared__ float tile[32][33];
    const int b = blockIdx.z;
    const int c0 = blockIdx.y * 32, n0 = blockIdx.x * 32;
    const int tx = threadIdx.x, ty = threadIdx.y;
    const float* xb = x + (long long)b * 16777216;
#pragma unroll
    for (int i = 0; i < 4; i++)
        tile[ty + i * 8][tx] = xb[(long long)(c0 + ty + i * 8) * 4096 + n0 + tx];
    __syncthreads();
#pragma unroll
    for (int i = 0; i < 4; i++) {
        float v = tile[tx][ty + i * 8];
        __nv_bfloat16 h = __float2bfloat16_rn(v);
        __nv_bfloat16 l = __float2bfloat16_rn(v - __bfloat162float(h));
        long long o = (long long)b * 16777216 + (long long)(n0 + ty + i * 8) * 4096 + c0 + tx;
        hi[o] = h; lo[o] = l; hf[o] = __float2half_rn(v);
    }
}

__global__ void transpose_split2_kernel(const float* __restrict__ w,
                                        __nv_bfloat16* __restrict__ hi,
                                        __nv_bfloat16* __restrict__ lo)
{
    __shared__ float tile[32][33];
    const int m0 = blockIdx.y * 32, n0 = blockIdx.x * 32;
    const int tx = threadIdx.x, ty = threadIdx.y;
#pragma unroll
    for (int i = 0; i < 4; i++)
        tile[ty + i * 8][tx] = w[(long long)(m0 + ty + i * 8) * 4096 + n0 + tx];
    __syncthreads();
#pragma unroll
    for (int i = 0; i < 4; i++) {
        float v = tile[tx][ty + i * 8];
        __nv_bfloat16 h = __float2bfloat16_rn(v);
        __nv_bfloat16 l = __float2bfloat16_rn(v - __bfloat162float(h));
        long long o = (long long)(n0 + ty + i * 8) * 4096 + m0 + tx;
        hi[o] = h; lo[o] = l;
    }
}

__global__ void wvec_kernel(const float* __restrict__ Wk,
                            const float* __restrict__ bq,
                            float* __restrict__ w)
{
    const int n = blockIdx.x * 256 + threadIdx.x;
    float acc = 0.0f;
    for (int m = 0; m < 4096; m++)
        acc += Wk[(long long)m * 4096 + n] * bq[m];
    w[n] = acc;
}

__global__ void beta_kernel(const __nv_bfloat16* __restrict__ qkv_h,
                            const __nv_bfloat16* __restrict__ qkv_l,
                            const float* __restrict__ w,
                            float* __restrict__ beta)
{
    const int bb = blockIdx.x;
    const int z = bb >> 9, d = bb & 511;
    const int b = z >> 3, h = z & 7;
    const long long row = (long long)(b * 8192 + 4096 + h * 512 + d) * 4096;
    __shared__ float red[256];
    const int t = threadIdx.x;
    float acc = 0.0f;
    for (int n = t; n < 4096; n += 256)
        acc += w[n] * (__bfloat162float(qkv_h[row + n]) + __bfloat162float(qkv_l[row + n]));
    red[t] = acc; __syncthreads();
#pragma unroll
    for (int s = 128; s > 0; s >>= 1) {
        if (t < s) red[t] += red[t + s];
        __syncthreads();
    }
    if (t == 0) beta[bb] = 0.125f * red[0];
}

__global__ void softmax_f16_kernel(const float* __restrict__ dot,
                                   const float* __restrict__ dot2,
                                   const float* __restrict__ beta,
                                   __half* __restrict__ attn)
{
    const long long row = blockIdx.x;
    const float* p = dot + row * 512;
    const float* p2 = dot2 + row * 512;
    const float* bb = beta + ((row >> 9) << 9);
    __shared__ float red[256];
    const int t = threadIdx.x;
    float v0 = p[t] + p2[t] + bb[t];
    float v1 = p[t + 256] + p2[t + 256] + bb[t + 256];
    red[t] = fmaxf(v0, v1); __syncthreads();
#pragma unroll
    for (int s = 128; s > 0; s >>= 1) {
        if (t < s) red[t] = fmaxf(red[t], red[t + s]);
        __syncthreads();
    }
    float mx = red[0]; __syncthreads();
    float e0 = expf(v0 - mx), e1 = expf(v1 - mx);
    red[t] = e0 + e1; __syncthreads();
#pragma unroll
    for (int s = 128; s > 0; s >>= 1) {
        if (t < s) red[t] += red[t + s];
        __syncthreads();
    }
    float inv = 1.0f / red[0];
    attn[row * 512 + t]       = __float2half_rn(e0 * inv);
    attn[row * 512 + t + 256] = __float2half_rn(e1 * inv);
}

// ---- host --------------------------------------------------------------------
extern "C" void kernel_launch(void* const* d_in, const int* in_sizes, int n_in,
                              void* d_out, int out_size)
{
    const float* x    = (const float*)d_in[0];
    const float* Wqkv = (const float*)d_in[1];
    const float* bqkv = (const float*)d_in[2];
    const float* Wq   = (const float*)d_in[3];
    const float* bq   = (const float*)d_in[4];
    const float* Wk   = (const float*)d_in[5];
    const float* bk   = (const float*)d_in[6];
    const float* Wv   = (const float*)d_in[7];
    const float* bv   = (const float*)d_in[8];
    const float* Wout = (const float*)d_in[9];
    const float* bout = (const float*)d_in[10];
    float* y = (float*)d_out;
    (void)bk;

    __nv_bfloat16 *xT_h, *xT_l, *Wqkv_h, *Wqkv_l, *WqT_h, *WqT_l, *WkT_h, *WkT_l,
        *qkv_h, *qkv_l, *q2_h, *q2_l, *H_h, *H_l;
    __half *xT_f, *Wqkv_vf, *Wv_f, *Wout_f, *v_f, *v2T_f, *attn_f, *outT_f;
    float *dot, *dot2, *wvec, *beta;
    cudaGetSymbolAddress((void**)&xT_h,   g_xT_hi);   cudaGetSymbolAddress((void**)&xT_l,   g_xT_lo);
    cudaGetSymbolAddress((void**)&xT_f,   g_xT_f);
    cudaGetSymbolAddress((void**)&Wqkv_h, g_Wqkv_hi); cudaGetSymbolAddress((void**)&Wqkv_l, g_Wqkv_lo);
    cudaGetSymbolAddress((void**)&Wqkv_vf,g_Wqkv_vf);
    cudaGetSymbolAddress((void**)&WqT_h,  g_WqT_hi);  cudaGetSymbolAddress((void**)&WqT_l,  g_WqT_lo);
    cudaGetSymbolAddress((void**)&WkT_h,  g_WkT_hi);  cudaGetSymbolAddress((void**)&WkT_l,  g_WkT_lo);
    cudaGetSymbolAddress((void**)&Wv_f,   g_Wv_f);    cudaGetSymbolAddress((void**)&Wout_f, g_Wout_f);
    cudaGetSymbolAddress((void**)&qkv_h,  g_qkv_hi);  cudaGetSymbolAddress((void**)&qkv_l,  g_qkv_lo);
    cudaGetSymbolAddress((void**)&v_f,    g_v_f);
    cudaGetSymbolAddress((void**)&q2_h,   g_q2_hi);   cudaGetSymbolAddress((void**)&q2_l,   g_q2_lo);
    cudaGetSymbolAddress((void**)&H_h,    g_H_hi);    cudaGetSymbolAddress((void**)&H_l,    g_H_lo);
    cudaGetSymbolAddress((void**)&v2T_f,  g_v2T_f);
    cudaGetSymbolAddress((void**)&attn_f, g_attn_f);
    cudaGetSymbolAddress((void**)&outT_f, g_outT_f);
    cudaGetSymbolAddress((void**)&dot,    g_dot);
    cudaGetSymbolAddress((void**)&dot2,   g_dot2);
    cudaGetSymbolAddress((void**)&wvec,   g_wvec);
    cudaGetSymbolAddress((void**)&beta,   g_beta);

    cudaFuncSetAttribute(hmma_gemm, cudaFuncAttributeMaxDynamicSharedMemorySize, SMEM_REQ);
    cudaFuncSetAttribute(hmma_gemm_f16, cudaFuncAttributeMaxDynamicSharedMemorySize, SMEM_REQ_H);

    static cudaStream_t s1 = nullptr;
    static cudaEvent_t e_root, e0, e1, eqk, eqg, eb, el2, esw;
    if (!s1) {
        cudaStreamCreateWithFlags(&s1, cudaStreamNonBlocking);
        cudaEventCreateWithFlags(&e_root, cudaEventDisableTiming);
        cudaEventCreateWithFlags(&e0,  cudaEventDisableTiming);
        cudaEventCreateWithFlags(&e1,  cudaEventDisableTiming);
        cudaEventCreateWithFlags(&eqk, cudaEventDisableTiming);
        cudaEventCreateWithFlags(&eqg, cudaEventDisableTiming);
        cudaEventCreateWithFlags(&eb,  cudaEventDisableTiming);
        cudaEventCreateWithFlags(&el2, cudaEventDisableTiming);
        cudaEventCreateWithFlags(&esw, cudaEventDisableTiming);
    }

    GemmP p;

    // ---- capture root on main; x conversion ----
    cudaEventRecord(e_root, 0);
    transpose_split_kernel<<<dim3(128, 128, 2), dim3(32, 8)>>>(x, xT_h, xT_l, xT_f);
    cudaEventRecord(e0, 0);

    // ---- side stream: weight conversions + H (pre-join, as in R13), then
    //      fork from e_root and run the Wqkv split as the first captured s1 op.
    transpose_split2_kernel<<<dim3(128, 128, 1), dim3(32, 8), 0, s1>>>(Wq, WqT_h, WqT_l);
    transpose_split2_kernel<<<dim3(128, 128, 1), dim3(32, 8), 0, s1>>>(Wk, WkT_h, WkT_l);
    half_kernel<<<16384, 256, 0, s1>>>((const float4*)Wv,   (uint2*)Wv_f,   4194304);
    half_kernel<<<16384, 256, 0, s1>>>((const float4*)Wout, (uint2*)Wout_f, 4194304);
    half_kernel<<<16384, 256, 0, s1>>>((const float4*)(Wqkv + 33554432LL), (uint2*)Wqkv_vf, 4194304);
    wvec_kernel<<<16, 256, 0, s1>>>(Wk, bq, wvec);
    p = {64, 4096, 4096, 0, 0,  0, 0, 0,  0, 0, 0,  0LL, 0LL,
         4096, 0, 1, nullptr, nullptr, H_h, H_l, 1.0f};
    hmma_gemm<<<dim3(32, 16, 1), 256, SMEM_REQ, s1>>>(WkT_h, WkT_l, WqT_h, WqT_l, p);
    cudaStreamWaitEvent(s1, e_root, 0);   // s1 joins capture at graph root
    split_kernel<<<32768, 256, 0, s1>>>((const float4*)Wqkv, (uint2*)Wqkv_h, (uint2*)Wqkv_l, 8388608);
    cudaEventRecord(esw, s1);             // in-capture event
    cudaStreamWaitEvent(s1, e0, 0);
    // Stage 1v (fp16)
    p = {64, 4096, 4096, 0, 0,  0, 0, 0,  4096, 0, 0,  16777216LL, 0,
         4096, 1, 2, bqkv + 8192, nullptr, (__nv_bfloat16*)v_f, nullptr, 1.0f};
    hmma_gemm_f16<<<dim3(32, 32, 2), 128, SMEM_REQ_H, s1>>>(Wqkv_vf, xT_f, p);
    // Stage 2v (fp16, transposed)
    p = {64, 4096, 4096, 3, 7,  0, 0, 0,  4096, 512, 0,  16777216LL, 2097152LL,
         512, 1, 2, bv, nullptr, (__nv_bfloat16*)v2T_f, nullptr, 1.0f};
    hmma_gemm_f16<<<dim3(4, 32, 16), 128, SMEM_REQ_H, s1>>>(Wv_f, v_f, p);
    cudaEventRecord(e1, s1);

    // ---- main: big q/k GEMM (waits for the in-capture Wqkv split) ----
    cudaStreamWaitEvent(0, esw, 0);
    p = {64, 4096, 4096, 0, 0,  0, 0, 0,  4096, 0, 0,  33554432LL, 0,
         4096, 1, 1, bqkv, nullptr, qkv_h, qkv_l, 1.0f};
    hmma_gemm<<<dim3(32, 32, 2), 256, SMEM_REQ>>>(Wqkv_h, Wqkv_l, xT_h, xT_l, p);
    cudaEventRecord(eqk, 0);

    // beta on s1 (needs qkv)
    cudaStreamWaitEvent(s1, eqk, 0);
    beta_kernel<<<8192, 256, 0, s1>>>(qkv_h, qkv_l, wvec, beta);
    cudaEventRecord(eb, s1);

    // ---- main: qG, logits (split-K), softmax, out ----
    cudaStreamWaitEvent(0, e1, 0);
    p = {64, 4096, 4096, 3, 7,  8192, 512, 0,  0, 0, 0,  16777216LL, 2097152LL,
         4096, 0, 1, nullptr, nullptr, q2_h, q2_l, 1.0f};
    hmma_gemm<<<dim3(32, 2, 16), 256, SMEM_REQ>>>(qkv_h, qkv_l, H_h, H_l, p);
    cudaEventRecord(eqg, 0);

    // logits half 2 on s1 (K = 2048..4095)
    cudaStreamWaitEvent(s1, eqg, 0);
    p = {32, 4096, 4096, 3, 7,  4096, 512, 0,  8192, 512, 4096,  2097152LL, 262144LL,
         512, 0, 0, nullptr, dot2, nullptr, nullptr, 0.125f};
    p.k0 = 2048;
    hmma_gemm<<<dim3(4, 2, 16), 256, SMEM_REQ, s1>>>(q2_h, q2_l, qkv_h, qkv_l, p);
    cudaEventRecord(el2, s1);

    // logits half 1 on main (K = 0..2047)
    p = {32, 4096, 4096, 3, 7,  4096, 512, 0,  8192, 512, 4096,  2097152LL, 262144LL,
         512, 0, 0, nullptr, dot, nullptr, nullptr, 0.125f};
    hmma_gemm<<<dim3(4, 2, 16), 256, SMEM_REQ>>>(q2_h, q2_l, qkv_h, qkv_l, p);

    cudaStreamWaitEvent(0, eb, 0);
    cudaStreamWaitEvent(0, el2, 0);
    softmax_f16_kernel<<<8192, 256>>>(dot, dot2, beta, attn_f);

    // Stage 5 (fp16, transposed)
    p = {8, 512, 512, 3, 7,  32768, 4096, 0,  4096, 512, 0,  16777216LL, 512LL,
         4096, 0, 2, nullptr, nullptr, (__nv_bfloat16*)outT_f, nullptr, 1.0f};
    hmma_gemm_f16<<<dim3(4, 32, 16), 128, SMEM_REQ_H>>>(v2T_f, attn_f, p);

    // Stage 6 (fp16): y = Wout @ outT^T + bout
    p = {64, 4096, 4096, 0, 0,  0, 0, 0,  4096, 0, 0,  16777216LL, 0,
         4096, 1, 0, bout, y, nullptr, nullptr, 1.0f};
    hmma_gemm_f16<<<dim3(32, 32, 2), 128, SMEM_REQ_H>>>(Wout_f, outT_f, p);

    (void)in_sizes; (void)n_in; (void)out_size;
}